// round 5
// baseline (speedup 1.0000x reference)
#include <cuda_runtime.h>
#include <cstdint>
#include <cstddef>

// ---------------------------------------------------------------------------
// ColorHistogramMatchingLoss
//   hist[b,c][i][j] = sum_n w_n * rbf(u_n)[i] * rbf(v_n)[j]   (a 64x64xN GEMM)
//   loss = mean_b sqrt(0.5 * sum (sqrt(hy/ty) - sqrt(hx/tx))^2)
// ---------------------------------------------------------------------------

#define D_HIST   64
#define CHUNK    64                    // pixels staged per iteration
#define SPLITS   16                    // pixel splits per (tensor,b,c)
#define NCHUNKS  64                    // (65536 / SPLITS) / CHUNK
#define HIST_BLOCKS (2*8*3*SPLITS)     // 768 blocks
#define EPS_F    1e-6f
#define PLANE    65536                 // 256*256

// scratch: 2 tensors x 8 batch x 3 combos x 64 x 64 (786 KB)
__device__ float g_hist[2*8*3*D_HIST*D_HIST];

// ---- packed f32x2 helpers (sm_103a FFMA2 is only reachable via PTX) -------
__device__ __forceinline__ unsigned long long pk2(float lo, float hi) {
    unsigned long long r;
    asm("mov.b64 %0, {%1, %2};" : "=l"(r) : "f"(lo), "f"(hi));
    return r;
}
__device__ __forceinline__ void fma2(unsigned long long &d,
                                     unsigned long long a,
                                     unsigned long long b) {
    asm("fma.rn.f32x2 %0, %1, %2, %0;" : "+l"(d) : "l"(a), "l"(b));
}

// ---------------------------------------------------------------------------
__global__ void zero_hist_kernel() {
    int i = blockIdx.x * blockDim.x + threadIdx.x;
    if (i < 2*8*3*D_HIST*D_HIST) g_hist[i] = 0.0f;
}

// ---------------------------------------------------------------------------
// One block handles one (tensor, b, c, split): 4096 pixels in 64-pixel chunks.
// Threads: 256. Four 64-thread groups; group g GEMMs k-slice [16g, 16g+16) of
// each chunk with an 8x8 per-thread f32x2 register tile of the 64x64 C.
// ---------------------------------------------------------------------------
__global__ __launch_bounds__(256, 2)
void hist_kernel(const float* __restrict__ x, const float* __restrict__ y) {
    __shared__ float A_sh[CHUNK][D_HIST];   // [k][i] = w_k * rbf_u(k, i)
    __shared__ float B_sh[CHUNK][D_HIST];   // [k][j] =       rbf_v(k, j)
    __shared__ float raw_sh[3][CHUNK];      // raw pixel values (3 channels)
    __shared__ float u_sh[CHUNK];           // u * 50
    __shared__ float v_sh[CHUNK];           // v * 50
    __shared__ float w_sh[CHUNK];           // pixel intensity weight

    const int bx     = blockIdx.x;
    const int split  = bx & (SPLITS - 1);
    const int r1     = bx >> 4;
    const int c      = r1 % 3;
    const int r2     = r1 / 3;
    const int b      = r2 & 7;
    const int tensor = r2 >> 3;

    const float* img = (tensor ? y : x) + (size_t)b * 3u * PLANE;

    const int t    = threadIdx.x;
    const int lcol = t & 63;      // column (bin index) in fill phase / pixel lane
    const int sel  = t >> 6;      // 0..3

    // bin center * 50 for this thread's column: (-3 + 6*i/63) * 50
    const float cs = fmaf((float)lcol, 300.0f/63.0f, -150.0f);

    // GEMM mapping: within 64-thread group, 8x8 thread grid, 8x8 tile each
    const int s     = t & 63;
    const int i0    = (s >> 3) * 8;
    const int j0    = (s & 7) * 8;
    const int kbase = sel * 16;

    unsigned long long acc[8][4];           // 8 rows x 4 f32x2 pairs (8 cols)
    #pragma unroll
    for (int ii = 0; ii < 8; ii++)
        #pragma unroll
        for (int jj = 0; jj < 4; jj++) acc[ii][jj] = 0ull;

    const int pixbase = split * (NCHUNKS * CHUNK);

    // prefetch chunk 0 raw pixels (threads with sel<3: one float each)
    float pref = 0.0f;
    if (sel < 3) pref = img[sel * PLANE + pixbase + lcol];

    const float* Ap = &A_sh[kbase][i0];
    const float* Bp = &B_sh[kbase][j0];

    for (int chk = 0; chk < NCHUNKS; ++chk) {
        // deposit prefetched raw values
        if (sel < 3) raw_sh[sel][lcol] = pref;
        __syncthreads();

        // per-pixel params (64 threads, one pixel each)
        if (t < CHUNK) {
            float rr = raw_sh[0][t] + EPS_F;
            float gg = raw_sh[1][t] + EPS_F;
            float bb = raw_sh[2][t] + EPS_F;
            float lr = logf(rr), lg = logf(gg), lb = logf(bb);
            float lc = (c == 0) ? lr : ((c == 1) ? lg : lb);
            float lu = (c == 0) ? lg : lr;   // u partner: r->g, g->r, b->r
            float lv = (c == 2) ? lg : lb;   // v partner: r->b, g->b, b->g
            u_sh[t] = (lc - lu) * 50.0f;
            v_sh[t] = (lc - lv) * 50.0f;
            w_sh[t] = sqrtf(fmaf(rr, rr, fmaf(gg, gg, bb * bb)));
        }
        // prefetch next chunk while fill+gemm run (hides DRAM latency)
        if (sel < 3 && chk + 1 < NCHUNKS)
            pref = img[sel * PLANE + pixbase + (chk + 1) * CHUNK + lcol];
        __syncthreads();

        // fill A/B column-parallel: lane = column -> conflict-free STS,
        // u/w reads are warp-broadcast. Center (cs) hoisted per thread.
        {
            const int k0 = (sel & 1) * 32;
            if (sel < 2) {
                #pragma unroll 8
                for (int k = 0; k < 32; k++) {
                    float tt = u_sh[k0 + k] - cs;
                    A_sh[k0 + k][lcol] = __fdividef(w_sh[k0 + k], fmaf(tt, tt, 1.0f));
                }
            } else {
                #pragma unroll 8
                for (int k = 0; k < 32; k++) {
                    float tt = v_sh[k0 + k] - cs;
                    B_sh[k0 + k][lcol] = __fdividef(1.0f, fmaf(tt, tt, 1.0f));
                }
            }
        }
        __syncthreads();

        // GEMM: 16 k-steps, 64 lane-FMAs/k via 32 packed f32x2 FMAs
        #pragma unroll
        for (int kk = 0; kk < 16; kk++) {
            float4 a0 = *(const float4*)(Ap + kk * D_HIST);
            float4 a1 = *(const float4*)(Ap + kk * D_HIST + 4);
            float4 b0 = *(const float4*)(Bp + kk * D_HIST);
            float4 b1 = *(const float4*)(Bp + kk * D_HIST + 4);
            unsigned long long pb0 = pk2(b0.x, b0.y);
            unsigned long long pb1 = pk2(b0.z, b0.w);
            unsigned long long pb2 = pk2(b1.x, b1.y);
            unsigned long long pb3 = pk2(b1.z, b1.w);
            #define HROW(idx, aval) { unsigned long long pa = pk2(aval, aval); \
                fma2(acc[idx][0], pa, pb0); fma2(acc[idx][1], pa, pb1);        \
                fma2(acc[idx][2], pa, pb2); fma2(acc[idx][3], pa, pb3); }
            HROW(0, a0.x) HROW(1, a0.y) HROW(2, a0.z) HROW(3, a0.w)
            HROW(4, a1.x) HROW(5, a1.y) HROW(6, a1.z) HROW(7, a1.w)
            #undef HROW
        }
        // no trailing sync needed: next iteration's two syncs order the
        // next A/B overwrite after every thread's GEMM of this chunk.
    }

    // ---- combine 4 group partials in shared, then RED.global ----
    __syncthreads();
    float* Csh = &A_sh[0][0];               // reuse 16 KB as 64x64 C buffer
    for (int i = t; i < D_HIST * D_HIST; i += 256) Csh[i] = 0.0f;
    __syncthreads();

    #pragma unroll
    for (int ii = 0; ii < 8; ii++) {
        #pragma unroll
        for (int jj = 0; jj < 4; jj++) {
            unsigned long long v = acc[ii][jj];
            float lo = __uint_as_float((unsigned)(v & 0xffffffffull));
            float hi = __uint_as_float((unsigned)(v >> 32));
            atomicAdd(&Csh[(i0 + ii) * D_HIST + j0 + 2 * jj],     lo);
            atomicAdd(&Csh[(i0 + ii) * D_HIST + j0 + 2 * jj + 1], hi);
        }
    }
    __syncthreads();

    float* dst = g_hist + (size_t)(((tensor * 8) + b) * 3 + c) * (D_HIST * D_HIST);
    for (int i = t; i < D_HIST * D_HIST; i += 256) atomicAdd(&dst[i], Csh[i]);
}

// ---------------------------------------------------------------------------
// Finalize: per-b totals, Hellinger-style distance, mean over batch.
// ---------------------------------------------------------------------------
__global__ __launch_bounds__(1024)
void finalize_kernel(float* __restrict__ out) {
    const int t = threadIdx.x;
    const int lane = t & 31;
    const int wp   = t >> 5;
    __shared__ float sred[32];
    __shared__ float sinvx[8], sinvy[8];
    const int PER_B = 3 * D_HIST * D_HIST;   // 12288

    // pass 1: totals
    for (int b = 0; b < 8; b++) {
        const float* hx = g_hist + (size_t)b * PER_B;
        const float* hy = g_hist + (size_t)(8 + b) * PER_B;
        float sx = 0.0f, sy = 0.0f;
        for (int i = t; i < PER_B; i += 1024) { sx += hx[i]; sy += hy[i]; }
        #pragma unroll
        for (int o = 16; o > 0; o >>= 1) {
            sx += __shfl_down_sync(0xffffffffu, sx, o);
            sy += __shfl_down_sync(0xffffffffu, sy, o);
        }
        __syncthreads();
        if (lane == 0) sred[wp] = sx;
        __syncthreads();
        if (t < 32) {
            float v = sred[t];
            #pragma unroll
            for (int o = 16; o > 0; o >>= 1) v += __shfl_down_sync(0xffffffffu, v, o);
            if (t == 0) sinvx[b] = 1.0f / v;
        }
        __syncthreads();
        if (lane == 0) sred[wp] = sy;
        __syncthreads();
        if (t < 32) {
            float v = sred[t];
            #pragma unroll
            for (int o = 16; o > 0; o >>= 1) v += __shfl_down_sync(0xffffffffu, v, o);
            if (t == 0) sinvy[b] = 1.0f / v;
        }
        __syncthreads();
    }

    // pass 2: sum (sqrt(hy/ty) - sqrt(hx/tx))^2 per b, then mean of sqrt(h/2)
    float loss = 0.0f;
    for (int b = 0; b < 8; b++) {
        const float* hx = g_hist + (size_t)b * PER_B;
        const float* hy = g_hist + (size_t)(8 + b) * PER_B;
        float ix = sinvx[b], iy = sinvy[b];
        float a = 0.0f;
        for (int i = t; i < PER_B; i += 1024) {
            float d = sqrtf(hy[i] * iy) - sqrtf(hx[i] * ix);
            a = fmaf(d, d, a);
        }
        #pragma unroll
        for (int o = 16; o > 0; o >>= 1) a += __shfl_down_sync(0xffffffffu, a, o);
        __syncthreads();
        if (lane == 0) sred[wp] = a;
        __syncthreads();
        if (t < 32) {
            float v = sred[t];
            #pragma unroll
            for (int o = 16; o > 0; o >>= 1) v += __shfl_down_sync(0xffffffffu, v, o);
            if (t == 0) loss += sqrtf(v * 0.5f);
        }
        __syncthreads();
    }
    if (t == 0) out[0] = loss * 0.125f;
}

// ---------------------------------------------------------------------------
extern "C" void kernel_launch(void* const* d_in, const int* in_sizes, int n_in,
                              void* d_out, int out_size) {
    (void)in_sizes; (void)n_in; (void)out_size;
    const float* x = (const float*)d_in[0];
    const float* y = (const float*)d_in[1];

    zero_hist_kernel<<<(2*8*3*D_HIST*D_HIST + 1023) / 1024, 1024>>>();
    hist_kernel<<<HIST_BLOCKS, 256>>>(x, y);
    finalize_kernel<<<1, 1024>>>((float*)d_out);
}